// round 13
// baseline (speedup 1.0000x reference)
#include <cuda_runtime.h>

#define M_SLOTS 16
#define KEY_DIM 1024
#define TPB     256
#define BUF     4                 // slots buffered to smem before the gate

// Handshake state. Zero-initialized at load; the last-finishing block of each
// launch resets everything, so every graph replay starts clean.
__device__ float        g_dot[M_SLOTS];
__device__ float        g_kk[M_SLOTS];
__device__ float        g_w[M_SLOTS];
__device__ unsigned int g_cnt;    // Phase-A arrival counter
__device__ unsigned int g_flag;   // 1 = weights published
__device__ unsigned int g_done;   // completion counter (reset duty)

// ---------------------------------------------------------------------------
// Phase A for blocks 0..15: block m computes slot m's partials in ONE parallel
// DRAM round-trip; the 16th arriver does the softmax and release-publishes.
// ---------------------------------------------------------------------------
__device__ __noinline__ void phase_a(const float* __restrict__ task_emb,
                                     const float* __restrict__ K_memory,
                                     int m) {
    __shared__ float s_dot[8], s_kk[8], s_tt[8];
    const int tid  = threadIdx.x;
    const int warp = tid >> 5;
    const int lane = tid & 31;

    float4 t = ((const float4*)task_emb)[tid];
    float4 k = ((const float4*)(K_memory + m * KEY_DIM))[tid];

    float dot = t.x * k.x + t.y * k.y + t.z * k.z + t.w * k.w;
    float kk  = k.x * k.x + k.y * k.y + k.z * k.z + k.w * k.w;
    float tt  = t.x * t.x + t.y * t.y + t.z * t.z + t.w * t.w;

    #pragma unroll
    for (int off = 16; off > 0; off >>= 1) {
        dot += __shfl_down_sync(0xffffffffu, dot, off);
        kk  += __shfl_down_sync(0xffffffffu, kk,  off);
        tt  += __shfl_down_sync(0xffffffffu, tt,  off);
    }
    if (lane == 0) { s_dot[warp] = dot; s_kk[warp] = kk; s_tt[warp] = tt; }
    __syncthreads();

    if (tid == 0) {
        float d = 0.f, q = 0.f, r = 0.f;
        #pragma unroll
        for (int w = 0; w < 8; w++) { d += s_dot[w]; q += s_kk[w]; r += s_tt[w]; }
        g_dot[m] = d;
        g_kk[m]  = q;
        __threadfence();
        unsigned int old = atomicAdd(&g_cnt, 1u);
        if (old == (unsigned)(M_SLOTS - 1)) {     // last arriver finalizes
            __threadfence();
            float n1 = sqrtf(r);
            float c[M_SLOTS];
            float mx = -1e30f;
            #pragma unroll
            for (int j = 0; j < M_SLOTS; j++) {
                c[j] = g_dot[j] / fmaxf(n1 * sqrtf(g_kk[j]), 1e-6f);
                mx = fmaxf(mx, c[j]);
            }
            float sum = 0.f;
            #pragma unroll
            for (int j = 0; j < M_SLOTS; j++) { c[j] = __expf(c[j] - mx); sum += c[j]; }
            float inv = 1.0f / sum;
            #pragma unroll
            for (int j = 0; j < M_SLOTS; j++) g_w[j] = c[j] * inv;
            __threadfence();
            unsigned int* fp = &g_flag;
            asm volatile("st.release.gpu.u32 [%0], %1;" :: "l"(fp), "r"(1u) : "memory");
        }
    }
}

// ---------------------------------------------------------------------------
// Single fused kernel, LOAD-FIRST / GATE-LAST:
//  1. (blocks 0..15) Phase A.
//  2. ALL blocks issue BUF slot-loads and park them in smem (STS anchors the
//     LDGs before the gate -> DRAM is busy during the rendezvous).
//  3. Spin gate on published weights.
//  4. Combine: BUF slots from smem + remaining slots with fresh loads.
// ---------------------------------------------------------------------------
__global__ void __launch_bounds__(TPB, 8) fused_kernel(
        const float*  __restrict__ task_emb,
        const float*  __restrict__ K_memory,
        const float4* __restrict__ V0,
        const float4* __restrict__ V1,
        float4*       __restrict__ out,
        int nv4_0, int nv4_1) {
    __shared__ float4 s_v[BUF * TPB];     // 16 KB
    __shared__ float  s_w[M_SLOTS];
    const int tid = threadIdx.x;

    // tile addressing
    const int i = blockIdx.x * TPB + tid;     // grid is an exact fit
    const float4* __restrict__ V;
    size_t stride;
    int idx;
    if (i < nv4_0) { V = V0; idx = i;          stride = (size_t)nv4_0; }
    else           { V = V1; idx = i - nv4_0;  stride = (size_t)nv4_1; }

    // 1) weights partials (16 blocks, ~one DRAM round-trip)
    if (blockIdx.x < M_SLOTS)
        phase_a(task_emb, K_memory, blockIdx.x);

    // 2) pre-issue BUF slot-loads; STS pins them before the gate
    #pragma unroll
    for (int m = 0; m < BUF; m++)
        s_v[m * TPB + tid] = V[(size_t)m * stride + (size_t)idx];

    // 3) gate: busy spin (overlapped with the in-flight loads above)
    if (tid == 0) {
        unsigned int* fp = &g_flag;
        unsigned int f;
        do {
            asm volatile("ld.acquire.gpu.u32 %0, [%1];" : "=r"(f) : "l"(fp) : "memory");
        } while (!f);
    }
    __syncthreads();                    // tid0's acquire orders the reads below
    if (tid < M_SLOTS) s_w[tid] = g_w[tid];
    __syncthreads();

    // 4) combine: smem-buffered slots then fresh-load slots (same m order)
    float4 acc = make_float4(0.f, 0.f, 0.f, 0.f);
    #pragma unroll
    for (int m = 0; m < BUF; m++) {
        float4 v = s_v[m * TPB + tid];
        float wm = s_w[m];
        acc.x = fmaf(wm, v.x, acc.x);
        acc.y = fmaf(wm, v.y, acc.y);
        acc.z = fmaf(wm, v.z, acc.z);
        acc.w = fmaf(wm, v.w, acc.w);
    }
    #pragma unroll
    for (int m = BUF; m < M_SLOTS; m++) {
        float4 v = V[(size_t)m * stride + (size_t)idx];
        float wm = s_w[m];
        acc.x = fmaf(wm, v.x, acc.x);
        acc.y = fmaf(wm, v.y, acc.y);
        acc.z = fmaf(wm, v.z, acc.z);
        acc.w = fmaf(wm, v.w, acc.w);
    }
    out[i] = acc;

    // reset handshake for the next graph replay
    if (tid == 0) {
        __threadfence();
        unsigned int d = atomicAdd(&g_done, 1u);
        if (d == gridDim.x - 1) {       // last block: all gates passed
            g_done = 0;
            g_flag = 0;
            g_cnt  = 0;
        }
    }
}

// ---------------------------------------------------------------------------
// Launch contract
// Inputs (metadata order): task_emb [1,1024] f32, K_memory [16,1024] f32,
//                          V0 [16,1024,1024] f32, V1 [16,1024,4096] f32
// Output: rec0 [1024,1024] f32 followed by rec1 [1024,4096] f32
// ---------------------------------------------------------------------------
extern "C" void kernel_launch(void* const* d_in, const int* in_sizes, int n_in,
                              void* d_out, int out_size) {
    const float* task_emb = (const float*)d_in[0];
    const float* K_memory = (const float*)d_in[1];
    const float* V0       = (const float*)d_in[2];
    const float* V1       = (const float*)d_in[3];
    float* out = (float*)d_out;

    const int n0 = in_sizes[2] / M_SLOTS;   // 1024*1024
    const int n1 = in_sizes[3] / M_SLOTS;   // 1024*4096
    const int nv4_0 = n0 / 4;               // 262144
    const int nv4_1 = n1 / 4;               // 1048576
    const int total = nv4_0 + nv4_1;        // 1310720 = 5120 * 256 exactly

    // Hint the carveout so 8 blocks x 16.5KB static smem fit comfortably.
    cudaFuncSetAttribute(fused_kernel,
                         cudaFuncAttributePreferredSharedMemoryCarveout, 100);

    fused_kernel<<<total / TPB, TPB>>>(task_emb, K_memory,
                                       (const float4*)V0, (const float4*)V1,
                                       (float4*)out, nv4_0, nv4_1);
}

// round 14
// speedup vs baseline: 1.1312x; 1.1312x over previous
#include <cuda_runtime.h>

#define M_SLOTS 16
#define KEY_DIM 1024
#define TPB     256
#define PRE     8                 // slots pre-loaded into registers before the gate

// Handshake state. Zero-initialized at load; the last-finishing block of each
// launch resets everything, so every graph replay starts clean.
__device__ float        g_dot[M_SLOTS];
__device__ float        g_kk[M_SLOTS];
__device__ float        g_w[M_SLOTS];
__device__ unsigned int g_cnt;    // Phase-A arrival counter
__device__ unsigned int g_flag;   // 1 = weights published
__device__ unsigned int g_done;   // completion counter (reset duty)

// ---------------------------------------------------------------------------
// Phase A for blocks 0..15: block m computes slot m's partials in one parallel
// DRAM round-trip; the 16th arriver does the softmax and release-publishes.
// ---------------------------------------------------------------------------
__device__ __noinline__ void phase_a(const float* __restrict__ task_emb,
                                     const float* __restrict__ K_memory,
                                     int m) {
    __shared__ float s_dot[8], s_kk[8], s_tt[8];
    const int tid  = threadIdx.x;
    const int warp = tid >> 5;
    const int lane = tid & 31;

    float4 t = ((const float4*)task_emb)[tid];
    float4 k = ((const float4*)(K_memory + m * KEY_DIM))[tid];

    float dot = t.x * k.x + t.y * k.y + t.z * k.z + t.w * k.w;
    float kk  = k.x * k.x + k.y * k.y + k.z * k.z + k.w * k.w;
    float tt  = t.x * t.x + t.y * t.y + t.z * t.z + t.w * t.w;

    #pragma unroll
    for (int off = 16; off > 0; off >>= 1) {
        dot += __shfl_down_sync(0xffffffffu, dot, off);
        kk  += __shfl_down_sync(0xffffffffu, kk,  off);
        tt  += __shfl_down_sync(0xffffffffu, tt,  off);
    }
    if (lane == 0) { s_dot[warp] = dot; s_kk[warp] = kk; s_tt[warp] = tt; }
    __syncthreads();

    if (tid == 0) {
        float d = 0.f, q = 0.f, r = 0.f;
        #pragma unroll
        for (int w = 0; w < 8; w++) { d += s_dot[w]; q += s_kk[w]; r += s_tt[w]; }
        g_dot[m] = d;
        g_kk[m]  = q;
        __threadfence();
        unsigned int old = atomicAdd(&g_cnt, 1u);
        if (old == (unsigned)(M_SLOTS - 1)) {     // last arriver finalizes
            __threadfence();
            float n1 = sqrtf(r);
            float c[M_SLOTS];
            float mx = -1e30f;
            #pragma unroll
            for (int j = 0; j < M_SLOTS; j++) {
                c[j] = g_dot[j] / fmaxf(n1 * sqrtf(g_kk[j]), 1e-6f);
                mx = fmaxf(mx, c[j]);
            }
            float sum = 0.f;
            #pragma unroll
            for (int j = 0; j < M_SLOTS; j++) { c[j] = __expf(c[j] - mx); sum += c[j]; }
            float inv = 1.0f / sum;
            #pragma unroll
            for (int j = 0; j < M_SLOTS; j++) g_w[j] = c[j] * inv;
            __threadfence();
            unsigned int* fp = &g_flag;
            asm volatile("st.release.gpu.u32 [%0], %1;" :: "l"(fp), "r"(1u) : "memory");
        }
    }
}

// ---------------------------------------------------------------------------
// Single fused kernel, loads IN FLIGHT across the gate:
//  1. (blocks 0..15) Phase A.
//  2. ALL blocks issue PRE volatile v4 loads into REGISTERS (no completion
//     forced, unlike R13's STS; volatile->volatile ordering stops ptxas from
//     sinking them below the spin, unlike R8's intrinsic).
//  3. tid0 busy-spins on the volatile acquire flag; __syncthreads.
//  4. Accumulate: PRE slots from registers + the rest with fresh loads.
// ---------------------------------------------------------------------------
__global__ void __launch_bounds__(TPB) fused_kernel(
        const float*  __restrict__ task_emb,
        const float*  __restrict__ K_memory,
        const float4* __restrict__ V0,
        const float4* __restrict__ V1,
        float4*       __restrict__ out,
        int nv4_0, int nv4_1) {
    __shared__ float s_w[M_SLOTS];
    const int tid = threadIdx.x;

    // tile addressing
    const int i = blockIdx.x * TPB + tid;     // grid is an exact fit
    const float4* __restrict__ V;
    size_t stride;
    int idx;
    if (i < nv4_0) { V = V0; idx = i;          stride = (size_t)nv4_0; }
    else           { V = V1; idx = i - nv4_0;  stride = (size_t)nv4_1; }

    // 1) weights partials (16 blocks, ~one DRAM round-trip)
    if (blockIdx.x < M_SLOTS)
        phase_a(task_emb, K_memory, blockIdx.x);

    // 2) pre-issue PRE loads into registers (volatile: pinned above the gate)
    float4 v[PRE];
    #pragma unroll
    for (int m = 0; m < PRE; m++) {
        const float4* p = V + (size_t)m * stride + (size_t)idx;
        asm volatile("ld.global.nc.v4.f32 {%0, %1, %2, %3}, [%4];"
                     : "=f"(v[m].x), "=f"(v[m].y), "=f"(v[m].z), "=f"(v[m].w)
                     : "l"(p));
    }

    // 3) gate: busy spin on the published flag (loads above stay in flight)
    if (tid == 0) {
        unsigned int* fp = &g_flag;
        unsigned int f;
        do {
            asm volatile("ld.acquire.gpu.u32 %0, [%1];" : "=r"(f) : "l"(fp) : "memory");
        } while (!f);
    }
    __syncthreads();                    // tid0's acquire orders the reads below
    if (tid < M_SLOTS) s_w[tid] = g_w[tid];
    __syncthreads();

    // 4) accumulate: register-buffered slots, then fresh-load slots
    float4 acc = make_float4(0.f, 0.f, 0.f, 0.f);
    #pragma unroll
    for (int m = 0; m < PRE; m++) {
        float wm = s_w[m];
        acc.x = fmaf(wm, v[m].x, acc.x);
        acc.y = fmaf(wm, v[m].y, acc.y);
        acc.z = fmaf(wm, v[m].z, acc.z);
        acc.w = fmaf(wm, v[m].w, acc.w);
    }
    #pragma unroll
    for (int m = PRE; m < M_SLOTS; m++) {
        float4 q = V[(size_t)m * stride + (size_t)idx];
        float wm = s_w[m];
        acc.x = fmaf(wm, q.x, acc.x);
        acc.y = fmaf(wm, q.y, acc.y);
        acc.z = fmaf(wm, q.z, acc.z);
        acc.w = fmaf(wm, q.w, acc.w);
    }
    out[i] = acc;

    // reset handshake for the next graph replay
    if (tid == 0) {
        __threadfence();
        unsigned int d = atomicAdd(&g_done, 1u);
        if (d == gridDim.x - 1) {       // last block: all gates passed
            g_done = 0;
            g_flag = 0;
            g_cnt  = 0;
        }
    }
}

// ---------------------------------------------------------------------------
// Launch contract
// Inputs (metadata order): task_emb [1,1024] f32, K_memory [16,1024] f32,
//                          V0 [16,1024,1024] f32, V1 [16,1024,4096] f32
// Output: rec0 [1024,1024] f32 followed by rec1 [1024,4096] f32
// ---------------------------------------------------------------------------
extern "C" void kernel_launch(void* const* d_in, const int* in_sizes, int n_in,
                              void* d_out, int out_size) {
    const float* task_emb = (const float*)d_in[0];
    const float* K_memory = (const float*)d_in[1];
    const float* V0       = (const float*)d_in[2];
    const float* V1       = (const float*)d_in[3];
    float* out = (float*)d_out;

    const int n0 = in_sizes[2] / M_SLOTS;   // 1024*1024
    const int n1 = in_sizes[3] / M_SLOTS;   // 1024*4096
    const int nv4_0 = n0 / 4;               // 262144
    const int nv4_1 = n1 / 4;               // 1048576
    const int total = nv4_0 + nv4_1;        // 1310720 = 5120 * 256 exactly

    fused_kernel<<<total / TPB, TPB>>>(task_emb, K_memory,
                                       (const float4*)V0, (const float4*)V1,
                                       (float4*)out, nv4_0, nv4_1);
}

// round 15
// speedup vs baseline: 1.2203x; 1.0788x over previous
#include <cuda_runtime.h>

#define M_SLOTS 16
#define KEY_DIM 1024
#define TPB     256

// softmax weights, produced by weights_kernel, consumed by wsum_kernel
__device__ float g_w[M_SLOTS];

// ---------------------------------------------------------------------------
// Kernel 1 (PDL primary): cosine similarity + softmax over 16 memory slots.
// ---------------------------------------------------------------------------
__global__ void __launch_bounds__(512) weights_kernel(
        const float* __restrict__ task_emb,
        const float* __restrict__ K_memory) {
#if __CUDA_ARCH__ >= 900
    cudaTriggerProgrammaticLaunchCompletion();
#endif
    __shared__ float s_cos[M_SLOTS];
    const int warp = threadIdx.x >> 5;
    const int lane = threadIdx.x & 31;

    const float4* t4 = (const float4*)task_emb;                 // 256 float4
    const float4* k4 = (const float4*)(K_memory + warp * KEY_DIM);

    float dot = 0.f, kk = 0.f, tt = 0.f;
    #pragma unroll
    for (int j = 0; j < 8; j++) {
        float4 t  = t4[lane + 32 * j];
        float4 km = k4[lane + 32 * j];
        dot = fmaf(t.x, km.x, dot); dot = fmaf(t.y, km.y, dot);
        dot = fmaf(t.z, km.z, dot); dot = fmaf(t.w, km.w, dot);
        kk  = fmaf(km.x, km.x, kk); kk  = fmaf(km.y, km.y, kk);
        kk  = fmaf(km.z, km.z, kk); kk  = fmaf(km.w, km.w, kk);
        tt  = fmaf(t.x,  t.x,  tt); tt  = fmaf(t.y,  t.y,  tt);
        tt  = fmaf(t.z,  t.z,  tt); tt  = fmaf(t.w,  t.w,  tt);
    }
    #pragma unroll
    for (int off = 16; off > 0; off >>= 1) {
        dot += __shfl_down_sync(0xffffffffu, dot, off);
        kk  += __shfl_down_sync(0xffffffffu, kk,  off);
        tt  += __shfl_down_sync(0xffffffffu, tt,  off);
    }
    if (lane == 0) {
        float denom = fmaxf(sqrtf(tt) * sqrtf(kk), 1e-6f);
        s_cos[warp] = dot / denom;
    }
    __syncthreads();

    if (threadIdx.x == 0) {
        float mx = -1e30f;
        #pragma unroll
        for (int m = 0; m < M_SLOTS; m++) mx = fmaxf(mx, s_cos[m]);
        float e[M_SLOTS];
        float sum = 0.f;
        #pragma unroll
        for (int m = 0; m < M_SLOTS; m++) {
            e[m] = __expf(s_cos[m] - mx);
            sum += e[m];
        }
        float inv = 1.0f / sum;
        #pragma unroll
        for (int m = 0; m < M_SLOTS; m++) g_w[m] = e[m] * inv;
    }
}

// ---------------------------------------------------------------------------
// Kernel 2 (PDL secondary): streaming weighted sum.
// Changes vs the proven 53.8us body:
//  - 2 float4 per thread (grid halved to 2560; V0 segment = 512-f4 multiple,
//    so block tiles never straddle the V0/V1 boundary) -> 32-deep MLP,
//    fewer waves, less tail raggedness.
//  - evict-first cache hints: ld.global.cs for V (read-once), st.global.cs
//    for out (write-once) -> no dead data competing in L2.
// ---------------------------------------------------------------------------
__global__ void __launch_bounds__(TPB) wsum_kernel(
        const float4* __restrict__ V0,
        const float4* __restrict__ V1,
        float4* __restrict__ out,
        int nv4_0, int nv4_1) {
    const int tid   = threadIdx.x;
    const int tile0 = blockIdx.x * (TPB * 2);     // 512 f4 per block, exact fit

    const float4* __restrict__ V;
    size_t stride;
    int base;
    if (tile0 < nv4_0) { V = V0; base = tile0;          stride = (size_t)nv4_0; }
    else               { V = V1; base = tile0 - nv4_0;  stride = (size_t)nv4_1; }

#if __CUDA_ARCH__ >= 900
    cudaGridDependencySynchronize();
#endif

    float w[M_SLOTS];
    #pragma unroll
    for (int m = 0; m < M_SLOTS; m++) w[m] = g_w[m];

    float4 acc0 = make_float4(0.f, 0.f, 0.f, 0.f);
    float4 acc1 = acc0;

    #pragma unroll
    for (int m = 0; m < M_SLOTS; m++) {
        const float4* p = V + (size_t)m * stride + (size_t)base + tid;
        float4 a, b;
        asm volatile("ld.global.cs.v4.f32 {%0, %1, %2, %3}, [%4];"
                     : "=f"(a.x), "=f"(a.y), "=f"(a.z), "=f"(a.w) : "l"(p));
        asm volatile("ld.global.cs.v4.f32 {%0, %1, %2, %3}, [%4];"
                     : "=f"(b.x), "=f"(b.y), "=f"(b.z), "=f"(b.w) : "l"(p + TPB));
        float wm = w[m];
        acc0.x = fmaf(wm, a.x, acc0.x); acc0.y = fmaf(wm, a.y, acc0.y);
        acc0.z = fmaf(wm, a.z, acc0.z); acc0.w = fmaf(wm, a.w, acc0.w);
        acc1.x = fmaf(wm, b.x, acc1.x); acc1.y = fmaf(wm, b.y, acc1.y);
        acc1.z = fmaf(wm, b.z, acc1.z); acc1.w = fmaf(wm, b.w, acc1.w);
    }

    float4* dst = out + tile0 + tid;
    asm volatile("st.global.cs.v4.f32 [%0], {%1, %2, %3, %4};"
                 :: "l"(dst), "f"(acc0.x), "f"(acc0.y), "f"(acc0.z), "f"(acc0.w)
                 : "memory");
    asm volatile("st.global.cs.v4.f32 [%0], {%1, %2, %3, %4};"
                 :: "l"(dst + TPB), "f"(acc1.x), "f"(acc1.y), "f"(acc1.z), "f"(acc1.w)
                 : "memory");
}

// ---------------------------------------------------------------------------
// Launch contract
// Inputs (metadata order): task_emb [1,1024] f32, K_memory [16,1024] f32,
//                          V0 [16,1024,1024] f32, V1 [16,1024,4096] f32
// Output: rec0 [1024,1024] f32 followed by rec1 [1024,4096] f32
// ---------------------------------------------------------------------------
extern "C" void kernel_launch(void* const* d_in, const int* in_sizes, int n_in,
                              void* d_out, int out_size) {
    const float* task_emb = (const float*)d_in[0];
    const float* K_memory = (const float*)d_in[1];
    const float* V0       = (const float*)d_in[2];
    const float* V1       = (const float*)d_in[3];
    float* out = (float*)d_out;

    const int n0 = in_sizes[2] / M_SLOTS;   // 1024*1024
    const int n1 = in_sizes[3] / M_SLOTS;   // 1024*4096
    const int nv4_0 = n0 / 4;               // 262144 (= 512 * 512, no straddle)
    const int nv4_1 = n1 / 4;               // 1048576
    const int total = nv4_0 + nv4_1;        // 1310720 = 2560 * 512 exactly

    weights_kernel<<<1, 512>>>(task_emb, K_memory);

    // Secondary with programmatic stream serialization (reproducibly +0.5us).
    cudaLaunchConfig_t cfg = {};
    cfg.gridDim  = dim3((unsigned)(total / (TPB * 2)));   // 2560
    cfg.blockDim = dim3(TPB);
    cfg.dynamicSmemBytes = 0;
    cfg.stream = 0;

    cudaLaunchAttribute attrs[1];
    attrs[0].id = cudaLaunchAttributeProgrammaticStreamSerialization;
    attrs[0].val.programmaticStreamSerializationAllowed = 1;
    cfg.attrs = attrs;
    cfg.numAttrs = 1;

    cudaLaunchKernelEx(&cfg, wsum_kernel,
                       (const float4*)V0, (const float4*)V1,
                       (float4*)out, nv4_0, nv4_1);
}